// round 15
// baseline (speedup 1.0000x reference)
#include <cuda_runtime.h>
#include <cuda_fp16.h>

#define MAX_N 50000
#define MAX_E 600000
#define D 128

// scratch (no allocation allowed -> __device__ globals)
__device__ __half g_h1[MAX_N * D];
__device__ __half g_agg1h[MAX_N * D];   // relu(layer1 agg), fp16
__device__ __half g_h2[MAX_N * D];
__device__ float  g_deg[MAX_N];
__device__ float  g_dis[MAX_N];
__device__ int    g_cnt[MAX_N];
__device__ int    g_cnt2[MAX_N];
__device__ int    g_rowptr[MAX_N];      // start offset per node (chunk-ticket order)
__device__ int    g_total;              // ticket allocator
__device__ int2   g_edge[MAX_E];        // (src_row, dis[src]*w bits) bucketed by dst col
// W packed in mma-fragment order: index (kk*16 + j)*32 + lane, payload {bh0,bh1,br0,br1}
__device__ uint4  g_Wp1[8 * 16 * 32];   // 64 KB
__device__ uint4  g_Wp2[8 * 16 * 32];

// ---------------- fused init: zero deg/cnt/cnt2/total + W fragment-pack ----------------
__device__ __forceinline__ unsigned packh2(float x, float y) {
    __half2 h = __floats2half2_rn(x, y);
    return *reinterpret_cast<unsigned*>(&h);
}
__device__ __forceinline__ unsigned packres2(float x, float y) {
    __half hx = __float2half_rn(x);
    __half hy = __float2half_rn(y);
    __half2 h = __floats2half2_rn(x - __half2float(hx), y - __half2float(hy));
    return *reinterpret_cast<unsigned*>(&h);
}

__global__ void prep_kernel(const float* __restrict__ W1, const float* __restrict__ W2, int n) {
    int i = blockIdx.x * blockDim.x + threadIdx.x;
    if (i == 0) g_total = 0;
    if (i < n) {
        g_deg[i] = 0.f;
        g_cnt[i] = 0;
        g_cnt2[i] = 0;
    }
    if (i < 8 * 16 * 32) {
        int lane = i & 31;
        int j = (i >> 5) & 15;
        int kk = i >> 9;
        int g = lane >> 2, tg = lane & 3;
        int wrow = j * 8 + g;
        int wcol = kk * 16 + tg * 2;
        const float* ws[2] = {W1, W2};
        uint4* wp[2] = {g_Wp1, g_Wp2};
        #pragma unroll
        for (int s = 0; s < 2; s++) {
            const float* W = ws[s];
            float w0 = W[wrow * D + wcol],     w1 = W[wrow * D + wcol + 1];
            float w8 = W[wrow * D + wcol + 8], w9 = W[wrow * D + wcol + 9];
            uint4 v;
            v.x = packh2(w0, w1);
            v.y = packh2(w8, w9);
            v.z = packres2(w0, w1);
            v.w = packres2(w8, w9);
            wp[s][i] = v;
        }
    }
}

// ---------------- CSR build (4 edges/thread, vector loads for MLP) ----------------
__global__ void hist_kernel(const float* __restrict__ w, const int* __restrict__ row,
                            const int* __restrict__ col, int E) {
    int t = blockIdx.x * blockDim.x + threadIdx.x;
    int e = t * 4;
    if (e + 3 < E) {
        int4 r4 = *(const int4*)(row + e);
        int4 c4 = *(const int4*)(col + e);
        float4 w4 = *(const float4*)(w + e);
        atomicAdd(&g_deg[r4.x], w4.x);
        atomicAdd(&g_deg[r4.y], w4.y);
        atomicAdd(&g_deg[r4.z], w4.z);
        atomicAdd(&g_deg[r4.w], w4.w);
        atomicAdd(&g_cnt[c4.x], 1);
        atomicAdd(&g_cnt[c4.y], 1);
        atomicAdd(&g_cnt[c4.z], 1);
        atomicAdd(&g_cnt[c4.w], 1);
    } else {
        for (; e < E; e++) {
            atomicAdd(&g_deg[row[e]], w[e]);
            atomicAdd(&g_cnt[col[e]], 1);
        }
    }
}

// single-pass: dis = rsqrt(deg); block-local scan of cnt; chunk base via atomic ticket.
__global__ void scan2_kernel(int n) {
    __shared__ int sa[256];
    __shared__ int sb[256];
    __shared__ int sbase;
    int t = threadIdx.x;
    int i = blockIdx.x * 256 + t;
    int c = (i < n) ? g_cnt[i] : 0;
    if (i < n) g_dis[i] = rsqrtf(g_deg[i]);
    sa[t] = c;
    __syncthreads();
    int* src = sa;
    int* dst = sb;
    #pragma unroll
    for (int off = 1; off < 256; off <<= 1) {
        int v = src[t];
        if (t >= off) v += src[t - off];
        dst[t] = v;
        __syncthreads();
        int* tmp = src; src = dst; dst = tmp;
    }
    if (t == 255) sbase = atomicAdd(&g_total, src[255]);
    __syncthreads();
    if (i < n) g_rowptr[i] = sbase + src[t] - c;  // exclusive within chunk + chunk base
}

// fill: edge payload = (src, dis[src]*w). dis[dst] is applied in the gather epilogue.
__device__ __forceinline__ void fill_one(int r, int c, float wv) {
    int pos = atomicAdd(&g_cnt2[c], 1);
    float nm = g_dis[r] * wv;
    g_edge[g_rowptr[c] + pos] = make_int2(r, __float_as_int(nm));
}

__global__ void fill_kernel(const float* __restrict__ w, const int* __restrict__ row,
                            const int* __restrict__ col, int E) {
    int t = blockIdx.x * blockDim.x + threadIdx.x;
    int e = t * 4;
    if (e + 3 < E) {
        int4 r4 = *(const int4*)(row + e);
        int4 c4 = *(const int4*)(col + e);
        float4 w4 = *(const float4*)(w + e);
        // batch the scattered reads first for MLP
        float d0 = g_dis[r4.x], d1 = g_dis[r4.y], d2 = g_dis[r4.z], d3 = g_dis[r4.w];
        int p0 = g_rowptr[c4.x], p1 = g_rowptr[c4.y], p2 = g_rowptr[c4.z], p3 = g_rowptr[c4.w];
        int q0 = atomicAdd(&g_cnt2[c4.x], 1);
        int q1 = atomicAdd(&g_cnt2[c4.y], 1);
        int q2 = atomicAdd(&g_cnt2[c4.z], 1);
        int q3 = atomicAdd(&g_cnt2[c4.w], 1);
        g_edge[p0 + q0] = make_int2(r4.x, __float_as_int(d0 * w4.x));
        g_edge[p1 + q1] = make_int2(r4.y, __float_as_int(d1 * w4.y));
        g_edge[p2 + q2] = make_int2(r4.z, __float_as_int(d2 * w4.z));
        g_edge[p3 + q3] = make_int2(r4.w, __float_as_int(d3 * w4.w));
    } else {
        for (; e < E; e++) fill_one(row[e], col[e], w[e]);
    }
}

// ---------------- tensor-core GEMM: out_h = fp16(X @ W^T + b) ----------------
// mma.sync.m16n8k16, fp16 in, fp32 accum, split-W (value + residual) for precision.
__device__ __forceinline__ void mma16816(float c[4], unsigned a0, unsigned a1,
                                         unsigned a2, unsigned a3,
                                         unsigned b0, unsigned b1) {
    asm("mma.sync.aligned.m16n8k16.row.col.f32.f16.f16.f32 "
        "{%0,%1,%2,%3},{%4,%5,%6,%7},{%8,%9},{%0,%1,%2,%3};"
        : "+f"(c[0]), "+f"(c[1]), "+f"(c[2]), "+f"(c[3])
        : "r"(a0), "r"(a1), "r"(a2), "r"(a3), "r"(b0), "r"(b1));
}

__device__ __forceinline__ unsigned h2u(__half2 h) { return *reinterpret_cast<unsigned*>(&h); }

template <bool A_FP32>
__global__ __launch_bounds__(256) void mma_gemm_kernel(const void* __restrict__ A_,
                                                       const uint4* __restrict__ Wp,
                                                       const float* __restrict__ bias,
                                                       __half* __restrict__ out, int n) {
    int warp = threadIdx.x >> 5;
    int lane = threadIdx.x & 31;
    int g = lane >> 2;
    int tg = lane & 3;
    int r0 = blockIdx.x * 128 + warp * 16;
    int rowA = r0 + g;
    int rowB = r0 + g + 8;
    bool vA = rowA < n, vB = rowB < n;

    const float* Af = (const float*)A_;
    const __half* Ah = (const __half*)A_;

    unsigned a[8][4];
    #pragma unroll
    for (int kk = 0; kk < 8; kk++) {
        int ka = kk * 16 + tg * 2;
        if (A_FP32) {
            float2 f0 = vA ? *(const float2*)(Af + (size_t)rowA * D + ka) : make_float2(0.f, 0.f);
            float2 f1 = vB ? *(const float2*)(Af + (size_t)rowB * D + ka) : make_float2(0.f, 0.f);
            float2 f2 = vA ? *(const float2*)(Af + (size_t)rowA * D + ka + 8) : make_float2(0.f, 0.f);
            float2 f3 = vB ? *(const float2*)(Af + (size_t)rowB * D + ka + 8) : make_float2(0.f, 0.f);
            a[kk][0] = h2u(__floats2half2_rn(f0.x, f0.y));
            a[kk][1] = h2u(__floats2half2_rn(f1.x, f1.y));
            a[kk][2] = h2u(__floats2half2_rn(f2.x, f2.y));
            a[kk][3] = h2u(__floats2half2_rn(f3.x, f3.y));
        } else {
            a[kk][0] = vA ? *(const unsigned*)(Ah + (size_t)rowA * D + ka) : 0u;
            a[kk][1] = vB ? *(const unsigned*)(Ah + (size_t)rowB * D + ka) : 0u;
            a[kk][2] = vA ? *(const unsigned*)(Ah + (size_t)rowA * D + ka + 8) : 0u;
            a[kk][3] = vB ? *(const unsigned*)(Ah + (size_t)rowB * D + ka + 8) : 0u;
        }
    }

    float c[16][4];
    #pragma unroll
    for (int j = 0; j < 16; j++)
        #pragma unroll
        for (int q = 0; q < 4; q++) c[j][q] = 0.f;

    #pragma unroll
    for (int kk = 0; kk < 8; kk++) {
        #pragma unroll
        for (int j = 0; j < 16; j++) {
            uint4 b = __ldg(&Wp[(kk * 16 + j) * 32 + lane]);  // coalesced 512B per warp
            mma16816(c[j], a[kk][0], a[kk][1], a[kk][2], a[kk][3], b.x, b.y);
            mma16816(c[j], a[kk][0], a[kk][1], a[kk][2], a[kk][3], b.z, b.w);
        }
    }

    #pragma unroll
    for (int j = 0; j < 16; j++) {
        int cc = j * 8 + tg * 2;
        float2 bv = *(const float2*)(bias + cc);
        if (vA) {
            __half2 o = __floats2half2_rn(c[j][0] + bv.x, c[j][1] + bv.y);
            *(__half2*)(out + (size_t)rowA * D + cc) = o;
        }
        if (vB) {
            __half2 o = __floats2half2_rn(c[j][2] + bv.x, c[j][3] + bv.y);
            *(__half2*)(out + (size_t)rowB * D + cc) = o;
        }
    }
}

// ---------------- gather: out[c] = dis[c] * sum_{e in bucket[c]} (dis[r]*w) * h[r] ----------------
__device__ __forceinline__ void gacc16(float acc[8], float nm, uint4 u) {
    float2 f0 = __half22float2(*(__half2*)&u.x);
    float2 f1 = __half22float2(*(__half2*)&u.y);
    float2 f2 = __half22float2(*(__half2*)&u.z);
    float2 f3 = __half22float2(*(__half2*)&u.w);
    acc[0] += nm * f0.x; acc[1] += nm * f0.y;
    acc[2] += nm * f1.x; acc[3] += nm * f1.y;
    acc[4] += nm * f2.x; acc[5] += nm * f2.y;
    acc[6] += nm * f3.x; acc[7] += nm * f3.y;
}

template <bool HALF_RELU_OUT>
__global__ void gather_kernel(const uint4* __restrict__ h, void* __restrict__ out_, int n) {
    int node = (blockIdx.x * blockDim.x + threadIdx.x) >> 5;
    int lane = threadIdx.x & 31;
    int lh = lane & 15;        // column chunk: cols lh*8 .. lh*8+7
    int half = lane >> 4;      // 0: even edges, 1: odd edges
    if (node >= n) return;
    int start = g_rowptr[node];
    int end = start + g_cnt[node];
    float disc = g_dis[node];

    float acc[8] = {0.f, 0.f, 0.f, 0.f, 0.f, 0.f, 0.f, 0.f};

    int j = start + half;
    for (; j + 6 < end; j += 8) {
        int2 e0 = g_edge[j];
        int2 e1 = g_edge[j + 2];
        int2 e2 = g_edge[j + 4];
        int2 e3 = g_edge[j + 6];
        uint4 u0 = __ldg(&h[(size_t)e0.x * 16 + lh]);
        uint4 u1 = __ldg(&h[(size_t)e1.x * 16 + lh]);
        uint4 u2 = __ldg(&h[(size_t)e2.x * 16 + lh]);
        uint4 u3 = __ldg(&h[(size_t)e3.x * 16 + lh]);
        gacc16(acc, __int_as_float(e0.y), u0);
        gacc16(acc, __int_as_float(e1.y), u1);
        gacc16(acc, __int_as_float(e2.y), u2);
        gacc16(acc, __int_as_float(e3.y), u3);
    }
    if (j + 2 < end) {
        int2 e0 = g_edge[j];
        int2 e1 = g_edge[j + 2];
        uint4 u0 = __ldg(&h[(size_t)e0.x * 16 + lh]);
        uint4 u1 = __ldg(&h[(size_t)e1.x * 16 + lh]);
        gacc16(acc, __int_as_float(e0.y), u0);
        gacc16(acc, __int_as_float(e1.y), u1);
        j += 4;
    }
    if (j < end) {
        int2 e0 = g_edge[j];
        uint4 u0 = __ldg(&h[(size_t)e0.x * 16 + lh]);
        gacc16(acc, __int_as_float(e0.y), u0);
    }

    #pragma unroll
    for (int q = 0; q < 8; q++) {
        acc[q] += __shfl_xor_sync(0xffffffff, acc[q], 16);
        acc[q] *= disc;   // deferred dis[dst] factor
    }

    if (half == 0) {
        if (HALF_RELU_OUT) {
            __half2 p0 = __floats2half2_rn(fmaxf(acc[0], 0.f), fmaxf(acc[1], 0.f));
            __half2 p1 = __floats2half2_rn(fmaxf(acc[2], 0.f), fmaxf(acc[3], 0.f));
            __half2 p2 = __floats2half2_rn(fmaxf(acc[4], 0.f), fmaxf(acc[5], 0.f));
            __half2 p3 = __floats2half2_rn(fmaxf(acc[6], 0.f), fmaxf(acc[7], 0.f));
            uint4 u;
            u.x = *reinterpret_cast<unsigned*>(&p0);
            u.y = *reinterpret_cast<unsigned*>(&p1);
            u.z = *reinterpret_cast<unsigned*>(&p2);
            u.w = *reinterpret_cast<unsigned*>(&p3);
            *(uint4*)((__half*)out_ + (size_t)node * D + lh * 8) = u;
        } else {
            float* dst = (float*)out_ + (size_t)node * D + lh * 8;
            *(float4*)dst = make_float4(acc[0], acc[1], acc[2], acc[3]);
            *(float4*)(dst + 4) = make_float4(acc[4], acc[5], acc[6], acc[7]);
        }
    }
}

extern "C" void kernel_launch(void* const* d_in, const int* in_sizes, int n_in,
                              void* d_out, int out_size) {
    const float* x  = (const float*)d_in[0];
    const int*   ei = (const int*)d_in[1];
    const float* ew = (const float*)d_in[2];
    const float* W1 = (const float*)d_in[3];
    const float* b1 = (const float*)d_in[4];
    const float* W2 = (const float*)d_in[5];
    const float* b2 = (const float*)d_in[6];
    float* out = (float*)d_out;

    int n = in_sizes[0] / D;
    int E = in_sizes[2];
    const int* row = ei;
    const int* col = ei + E;

    void *p_h1, *p_agg1h, *p_h2, *p_Wp1, *p_Wp2;
    cudaGetSymbolAddress(&p_h1, g_h1);
    cudaGetSymbolAddress(&p_agg1h, g_agg1h);
    cudaGetSymbolAddress(&p_h2, g_h2);
    cudaGetSymbolAddress(&p_Wp1, g_Wp1);
    cudaGetSymbolAddress(&p_Wp2, g_Wp2);

    int nb = (n + 255) / 256;
    int ne4 = (E + 3) / 4;             // threads for 4-edge kernels
    int eb4 = (ne4 + 255) / 256;

    // prep: fused init + W pack; hist; single-pass scan (atomic ticket); fill
    prep_kernel<<<nb, 256>>>(W1, W2, n);
    hist_kernel<<<eb4, 256>>>(ew, row, col, E);
    scan2_kernel<<<nb, 256>>>(n);
    fill_kernel<<<eb4, 256>>>(ew, row, col, E);

    int gemm_blocks = (n + 127) / 128;
    int gather_blocks = (n * 32 + 255) / 256;

    // layer 1 (tensor GEMM fp32 in -> fp16 h1, gather -> relu fp16 agg1h)
    mma_gemm_kernel<true><<<gemm_blocks, 256>>>(x, (const uint4*)p_Wp1, b1, (__half*)p_h1, n);
    gather_kernel<true><<<gather_blocks, 256>>>((const uint4*)p_h1, p_agg1h, n);

    // layer 2 (tensor GEMM fp16 in -> fp16 h2, gather -> fp32 out)
    mma_gemm_kernel<false><<<gemm_blocks, 256>>>(p_agg1h, (const uint4*)p_Wp2, b2, (__half*)p_h2, n);
    gather_kernel<false><<<gather_blocks, 256>>>((const uint4*)p_h2, out, n);
}

// round 17
// speedup vs baseline: 1.0146x; 1.0146x over previous
#include <cuda_runtime.h>
#include <cuda_fp16.h>

#define MAX_N 50000
#define MAX_E 600000
#define D 128

// scratch (no allocation allowed -> __device__ globals)
__device__ __half g_h1[MAX_N * D];
__device__ __half g_agg1h[MAX_N * D];   // relu(layer1 agg), fp16
__device__ __half g_h2[MAX_N * D];
__device__ float  g_deg[MAX_N];
__device__ float  g_dis[MAX_N];
__device__ int    g_cnt[MAX_N];
__device__ int    g_cnt2[MAX_N];        // slot cursor (initialized to rowptr base)
__device__ int2   g_meta[MAX_N];        // (start, cnt) per node
__device__ int    g_total;              // ticket allocator
__device__ int2   g_edge[MAX_E];        // (src_row, dis[src]*w bits) bucketed by dst col
// W packed in mma-fragment order: index (kk*16 + j)*32 + lane, payload {bh0,bh1,br0,br1}
__device__ uint4  g_Wp1[8 * 16 * 32];   // 64 KB
__device__ uint4  g_Wp2[8 * 16 * 32];

// ---------------- zero init (graph-prep stream) ----------------
__global__ void zero_kernel(int n) {
    int i = blockIdx.x * blockDim.x + threadIdx.x;
    if (i == 0) g_total = 0;
    if (i < n) {
        g_deg[i] = 0.f;
        g_cnt[i] = 0;
    }
}

// ---------------- W fragment-pack (gemm stream) ----------------
__device__ __forceinline__ unsigned packh2(float x, float y) {
    __half2 h = __floats2half2_rn(x, y);
    return *reinterpret_cast<unsigned*>(&h);
}
__device__ __forceinline__ unsigned packres2(float x, float y) {
    __half hx = __float2half_rn(x);
    __half hy = __float2half_rn(y);
    __half2 h = __floats2half2_rn(x - __half2float(hx), y - __half2float(hy));
    return *reinterpret_cast<unsigned*>(&h);
}

__global__ void wpack_kernel(const float* __restrict__ W1, const float* __restrict__ W2) {
    int i = blockIdx.x * blockDim.x + threadIdx.x;
    if (i >= 8 * 16 * 32) return;
    int lane = i & 31;
    int j = (i >> 5) & 15;
    int kk = i >> 9;
    int g = lane >> 2, tg = lane & 3;
    int wrow = j * 8 + g;
    int wcol = kk * 16 + tg * 2;
    const float* ws[2] = {W1, W2};
    uint4* wp[2] = {g_Wp1, g_Wp2};
    #pragma unroll
    for (int s = 0; s < 2; s++) {
        const float* W = ws[s];
        float w0 = W[wrow * D + wcol],     w1 = W[wrow * D + wcol + 1];
        float w8 = W[wrow * D + wcol + 8], w9 = W[wrow * D + wcol + 9];
        uint4 v;
        v.x = packh2(w0, w1);
        v.y = packh2(w8, w9);
        v.z = packres2(w0, w1);
        v.w = packres2(w8, w9);
        wp[s][i] = v;
    }
}

// ---------------- CSR build (4 edges/thread, vector loads for MLP) ----------------
__global__ void hist_kernel(const float* __restrict__ w, const int* __restrict__ row,
                            const int* __restrict__ col, int E) {
    int t = blockIdx.x * blockDim.x + threadIdx.x;
    int e = t * 4;
    if (e + 3 < E) {
        int4 r4 = *(const int4*)(row + e);
        int4 c4 = *(const int4*)(col + e);
        float4 w4 = *(const float4*)(w + e);
        atomicAdd(&g_deg[r4.x], w4.x);
        atomicAdd(&g_deg[r4.y], w4.y);
        atomicAdd(&g_deg[r4.z], w4.z);
        atomicAdd(&g_deg[r4.w], w4.w);
        atomicAdd(&g_cnt[c4.x], 1);
        atomicAdd(&g_cnt[c4.y], 1);
        atomicAdd(&g_cnt[c4.z], 1);
        atomicAdd(&g_cnt[c4.w], 1);
    } else {
        for (; e < E; e++) {
            atomicAdd(&g_deg[row[e]], w[e]);
            atomicAdd(&g_cnt[col[e]], 1);
        }
    }
}

// single-pass: dis = rsqrt(deg); block-local scan of cnt; chunk base via atomic ticket.
// Writes g_cnt2 = start (fill cursor) and g_meta = (start, cnt) for gather.
__global__ void scan2_kernel(int n) {
    __shared__ int sa[256];
    __shared__ int sb[256];
    __shared__ int sbase;
    int t = threadIdx.x;
    int i = blockIdx.x * 256 + t;
    int c = (i < n) ? g_cnt[i] : 0;
    if (i < n) g_dis[i] = rsqrtf(g_deg[i]);
    sa[t] = c;
    __syncthreads();
    int* src = sa;
    int* dst = sb;
    #pragma unroll
    for (int off = 1; off < 256; off <<= 1) {
        int v = src[t];
        if (t >= off) v += src[t - off];
        dst[t] = v;
        __syncthreads();
        int* tmp = src; src = dst; dst = tmp;
    }
    if (t == 255) sbase = atomicAdd(&g_total, src[255]);
    __syncthreads();
    if (i < n) {
        int start = sbase + src[t] - c;
        g_cnt2[i] = start;               // absolute slot cursor for fill
        g_meta[i] = make_int2(start, c); // gather metadata
    }
}

// fill: edge payload = (src, dis[src]*w); atomic cursor gives absolute slot directly.
__device__ __forceinline__ void fill_one(int r, int c, float wv) {
    int pos = atomicAdd(&g_cnt2[c], 1);
    g_edge[pos] = make_int2(r, __float_as_int(g_dis[r] * wv));
}

__global__ void fill_kernel(const float* __restrict__ w, const int* __restrict__ row,
                            const int* __restrict__ col, int E) {
    int t = blockIdx.x * blockDim.x + threadIdx.x;
    int e = t * 4;
    if (e + 3 < E) {
        int4 r4 = *(const int4*)(row + e);
        int4 c4 = *(const int4*)(col + e);
        float4 w4 = *(const float4*)(w + e);
        // batch independent scattered chains for MLP
        float d0 = g_dis[r4.x], d1 = g_dis[r4.y], d2 = g_dis[r4.z], d3 = g_dis[r4.w];
        int q0 = atomicAdd(&g_cnt2[c4.x], 1);
        int q1 = atomicAdd(&g_cnt2[c4.y], 1);
        int q2 = atomicAdd(&g_cnt2[c4.z], 1);
        int q3 = atomicAdd(&g_cnt2[c4.w], 1);
        g_edge[q0] = make_int2(r4.x, __float_as_int(d0 * w4.x));
        g_edge[q1] = make_int2(r4.y, __float_as_int(d1 * w4.y));
        g_edge[q2] = make_int2(r4.z, __float_as_int(d2 * w4.z));
        g_edge[q3] = make_int2(r4.w, __float_as_int(d3 * w4.w));
    } else {
        for (; e < E; e++) fill_one(row[e], col[e], w[e]);
    }
}

// ---------------- tensor-core GEMM: out_h = fp16(X @ W^T + b) ----------------
// mma.sync.m16n8k16, fp16 in, fp32 accum, split-W (value + residual) for precision.
__device__ __forceinline__ void mma16816(float c[4], unsigned a0, unsigned a1,
                                         unsigned a2, unsigned a3,
                                         unsigned b0, unsigned b1) {
    asm("mma.sync.aligned.m16n8k16.row.col.f32.f16.f16.f32 "
        "{%0,%1,%2,%3},{%4,%5,%6,%7},{%8,%9},{%0,%1,%2,%3};"
        : "+f"(c[0]), "+f"(c[1]), "+f"(c[2]), "+f"(c[3])
        : "r"(a0), "r"(a1), "r"(a2), "r"(a3), "r"(b0), "r"(b1));
}

__device__ __forceinline__ unsigned h2u(__half2 h) { return *reinterpret_cast<unsigned*>(&h); }

template <bool A_FP32>
__global__ __launch_bounds__(256) void mma_gemm_kernel(const void* __restrict__ A_,
                                                       const uint4* __restrict__ Wp,
                                                       const float* __restrict__ bias,
                                                       __half* __restrict__ out, int n) {
    int warp = threadIdx.x >> 5;
    int lane = threadIdx.x & 31;
    int g = lane >> 2;
    int tg = lane & 3;
    int r0 = blockIdx.x * 128 + warp * 16;
    int rowA = r0 + g;
    int rowB = r0 + g + 8;
    bool vA = rowA < n, vB = rowB < n;

    const float* Af = (const float*)A_;
    const __half* Ah = (const __half*)A_;

    unsigned a[8][4];
    #pragma unroll
    for (int kk = 0; kk < 8; kk++) {
        int ka = kk * 16 + tg * 2;
        if (A_FP32) {
            float2 f0 = vA ? *(const float2*)(Af + (size_t)rowA * D + ka) : make_float2(0.f, 0.f);
            float2 f1 = vB ? *(const float2*)(Af + (size_t)rowB * D + ka) : make_float2(0.f, 0.f);
            float2 f2 = vA ? *(const float2*)(Af + (size_t)rowA * D + ka + 8) : make_float2(0.f, 0.f);
            float2 f3 = vB ? *(const float2*)(Af + (size_t)rowB * D + ka + 8) : make_float2(0.f, 0.f);
            a[kk][0] = h2u(__floats2half2_rn(f0.x, f0.y));
            a[kk][1] = h2u(__floats2half2_rn(f1.x, f1.y));
            a[kk][2] = h2u(__floats2half2_rn(f2.x, f2.y));
            a[kk][3] = h2u(__floats2half2_rn(f3.x, f3.y));
        } else {
            a[kk][0] = vA ? *(const unsigned*)(Ah + (size_t)rowA * D + ka) : 0u;
            a[kk][1] = vB ? *(const unsigned*)(Ah + (size_t)rowB * D + ka) : 0u;
            a[kk][2] = vA ? *(const unsigned*)(Ah + (size_t)rowA * D + ka + 8) : 0u;
            a[kk][3] = vB ? *(const unsigned*)(Ah + (size_t)rowB * D + ka + 8) : 0u;
        }
    }

    float c[16][4];
    #pragma unroll
    for (int j = 0; j < 16; j++)
        #pragma unroll
        for (int q = 0; q < 4; q++) c[j][q] = 0.f;

    #pragma unroll
    for (int kk = 0; kk < 8; kk++) {
        #pragma unroll
        for (int j = 0; j < 16; j++) {
            uint4 b = __ldg(&Wp[(kk * 16 + j) * 32 + lane]);  // coalesced 512B per warp
            mma16816(c[j], a[kk][0], a[kk][1], a[kk][2], a[kk][3], b.x, b.y);
            mma16816(c[j], a[kk][0], a[kk][1], a[kk][2], a[kk][3], b.z, b.w);
        }
    }

    #pragma unroll
    for (int j = 0; j < 16; j++) {
        int cc = j * 8 + tg * 2;
        float2 bv = *(const float2*)(bias + cc);
        if (vA) {
            __half2 o = __floats2half2_rn(c[j][0] + bv.x, c[j][1] + bv.y);
            *(__half2*)(out + (size_t)rowA * D + cc) = o;
        }
        if (vB) {
            __half2 o = __floats2half2_rn(c[j][2] + bv.x, c[j][3] + bv.y);
            *(__half2*)(out + (size_t)rowB * D + cc) = o;
        }
    }
}

// ---------------- gather: out[c] = dis[c] * sum_{e in bucket[c]} (dis[r]*w) * h[r] ----------------
__device__ __forceinline__ void gacc16(float acc[8], float nm, uint4 u) {
    float2 f0 = __half22float2(*(__half2*)&u.x);
    float2 f1 = __half22float2(*(__half2*)&u.y);
    float2 f2 = __half22float2(*(__half2*)&u.z);
    float2 f3 = __half22float2(*(__half2*)&u.w);
    acc[0] += nm * f0.x; acc[1] += nm * f0.y;
    acc[2] += nm * f1.x; acc[3] += nm * f1.y;
    acc[4] += nm * f2.x; acc[5] += nm * f2.y;
    acc[6] += nm * f3.x; acc[7] += nm * f3.y;
}

template <bool HALF_RELU_OUT>
__global__ void gather_kernel(const uint4* __restrict__ h, void* __restrict__ out_, int n) {
    int node = (blockIdx.x * blockDim.x + threadIdx.x) >> 5;
    int lane = threadIdx.x & 31;
    int lh = lane & 15;        // column chunk: cols lh*8 .. lh*8+7
    int half = lane >> 4;      // 0: even edges, 1: odd edges
    if (node >= n) return;
    int2 meta = g_meta[node];
    int start = meta.x;
    int end = start + meta.y;
    float disc = g_dis[node];

    float acc[8] = {0.f, 0.f, 0.f, 0.f, 0.f, 0.f, 0.f, 0.f};

    int j = start + half;
    for (; j + 6 < end; j += 8) {
        int2 e0 = g_edge[j];
        int2 e1 = g_edge[j + 2];
        int2 e2 = g_edge[j + 4];
        int2 e3 = g_edge[j + 6];
        uint4 u0 = __ldg(&h[(size_t)e0.x * 16 + lh]);
        uint4 u1 = __ldg(&h[(size_t)e1.x * 16 + lh]);
        uint4 u2 = __ldg(&h[(size_t)e2.x * 16 + lh]);
        uint4 u3 = __ldg(&h[(size_t)e3.x * 16 + lh]);
        gacc16(acc, __int_as_float(e0.y), u0);
        gacc16(acc, __int_as_float(e1.y), u1);
        gacc16(acc, __int_as_float(e2.y), u2);
        gacc16(acc, __int_as_float(e3.y), u3);
    }
    if (j + 2 < end) {
        int2 e0 = g_edge[j];
        int2 e1 = g_edge[j + 2];
        uint4 u0 = __ldg(&h[(size_t)e0.x * 16 + lh]);
        uint4 u1 = __ldg(&h[(size_t)e1.x * 16 + lh]);
        gacc16(acc, __int_as_float(e0.y), u0);
        gacc16(acc, __int_as_float(e1.y), u1);
        j += 4;
    }
    if (j < end) {
        int2 e0 = g_edge[j];
        uint4 u0 = __ldg(&h[(size_t)e0.x * 16 + lh]);
        gacc16(acc, __int_as_float(e0.y), u0);
    }

    #pragma unroll
    for (int q = 0; q < 8; q++) {
        acc[q] += __shfl_xor_sync(0xffffffff, acc[q], 16);
        acc[q] *= disc;   // deferred dis[dst] factor
    }

    if (half == 0) {
        if (HALF_RELU_OUT) {
            __half2 p0 = __floats2half2_rn(fmaxf(acc[0], 0.f), fmaxf(acc[1], 0.f));
            __half2 p1 = __floats2half2_rn(fmaxf(acc[2], 0.f), fmaxf(acc[3], 0.f));
            __half2 p2 = __floats2half2_rn(fmaxf(acc[4], 0.f), fmaxf(acc[5], 0.f));
            __half2 p3 = __floats2half2_rn(fmaxf(acc[6], 0.f), fmaxf(acc[7], 0.f));
            uint4 u;
            u.x = *reinterpret_cast<unsigned*>(&p0);
            u.y = *reinterpret_cast<unsigned*>(&p1);
            u.z = *reinterpret_cast<unsigned*>(&p2);
            u.w = *reinterpret_cast<unsigned*>(&p3);
            *(uint4*)((__half*)out_ + (size_t)node * D + lh * 8) = u;
        } else {
            float* dst = (float*)out_ + (size_t)node * D + lh * 8;
            *(float4*)dst = make_float4(acc[0], acc[1], acc[2], acc[3]);
            *(float4*)(dst + 4) = make_float4(acc[4], acc[5], acc[6], acc[7]);
        }
    }
}

extern "C" void kernel_launch(void* const* d_in, const int* in_sizes, int n_in,
                              void* d_out, int out_size) {
    const float* x  = (const float*)d_in[0];
    const int*   ei = (const int*)d_in[1];
    const float* ew = (const float*)d_in[2];
    const float* W1 = (const float*)d_in[3];
    const float* b1 = (const float*)d_in[4];
    const float* W2 = (const float*)d_in[5];
    const float* b2 = (const float*)d_in[6];
    float* out = (float*)d_out;

    int n = in_sizes[0] / D;
    int E = in_sizes[2];
    const int* row = ei;
    const int* col = ei + E;

    void *p_h1, *p_agg1h, *p_h2, *p_Wp1, *p_Wp2;
    cudaGetSymbolAddress(&p_h1, g_h1);
    cudaGetSymbolAddress(&p_agg1h, g_agg1h);
    cudaGetSymbolAddress(&p_h2, g_h2);
    cudaGetSymbolAddress(&p_Wp1, g_Wp1);
    cudaGetSymbolAddress(&p_Wp2, g_Wp2);

    // one-time side stream + events (host resources, created once; work per call identical)
    static cudaStream_t sB = nullptr;
    static cudaEvent_t evFork = nullptr, evB = nullptr;
    if (!sB) {
        cudaStreamCreateWithFlags(&sB, cudaStreamNonBlocking);
        cudaEventCreateWithFlags(&evFork, cudaEventDisableTiming);
        cudaEventCreateWithFlags(&evB, cudaEventDisableTiming);
    }

    int nb = (n + 255) / 256;
    int ne4 = (E + 3) / 4;
    int eb4 = (ne4 + 255) / 256;
    int gemm_blocks = (n + 127) / 128;
    int gather_blocks = (n * 32 + 255) / 256;

    // fork: side stream runs W-pack + layer-1 GEMM (depends only on x, W1)
    cudaEventRecord(evFork, 0);
    cudaStreamWaitEvent(sB, evFork, 0);
    wpack_kernel<<<(8 * 16 * 32 + 255) / 256, 256, 0, sB>>>(W1, W2);
    mma_gemm_kernel<true><<<gemm_blocks, 256, 0, sB>>>(x, (const uint4*)p_Wp1, b1,
                                                       (__half*)p_h1, n);
    cudaEventRecord(evB, sB);

    // main stream: graph prep chain
    zero_kernel<<<nb, 256>>>(n);
    hist_kernel<<<eb4, 256>>>(ew, row, col, E);
    scan2_kernel<<<nb, 256>>>(n);
    fill_kernel<<<eb4, 256>>>(ew, row, col, E);

    // join: gather1 needs fill (main) + h1 (side)
    cudaStreamWaitEvent(0, evB, 0);
    gather_kernel<true><<<gather_blocks, 256>>>((const uint4*)p_h1, p_agg1h, n);

    // layer 2
    mma_gemm_kernel<false><<<gemm_blocks, 256>>>(p_agg1h, (const uint4*)p_Wp2, b2,
                                                 (__half*)p_h2, n);
    gather_kernel<false><<<gather_blocks, 256>>>((const uint4*)p_h2, out, n);
}